// round 11
// baseline (speedup 1.0000x reference)
#include <cuda_runtime.h>
#include <cstdint>

#define BGRAPHS   16
#define NPG       2048
#define KNN       16
#define MIN_DISTR 5
#define CPB       64                 // centers per block (2 per thread)
#define PARTS     8                  // parts per center
#define CANDS     (NPG / PARTS)      // 256 candidates per part
#define THREADS   256                // (CPB/2) * PARTS
#define CAP       128                // pass-2 collection capacity per center

// monotone float -> uint key (total order matching float <)
__device__ __forceinline__ unsigned sortkey(float f)
{
    unsigned u = __float_as_uint(f);
    return u ^ (unsigned)(((int)u >> 31) | 0x80000000);
}

// exact reference-rounded squared distance (validated rounds 3-10)
__device__ __forceinline__ float d2_ref(float cx, float cy, float cz, float csq,
                                        const float4 v)
{
    float dot = __fmaf_rn(cz, v.z, __fmaf_rn(cy, v.y, __fmul_rn(cx, v.x)));
    return __fmaf_rn(-2.0f, dot, __fadd_rn(csq, v.w));
}

__global__ __launch_bounds__(THREADS, 4)
void knn_kernel(const float* __restrict__ pos, float2* __restrict__ out)
{
    __shared__ float4         sh[NPG];                // 32768 B: x,y,z,|p|^2
    __shared__ float          pvals[CPB * PARTS * 3]; //  6144 B: per-part 3 smallest
    __shared__ float          bnd[CPB];               //   256 B
    __shared__ int            cnt[CPB];               //   256 B
    __shared__ unsigned short jbuf[CPB * CAP];        // 16384 B   (total ~55.8 KB)

    const int tid = threadIdx.x;
    const int p   = tid >> 5;        // part 0..7 (uniform per warp)
    const int c   = tid & 31;        // first center (lane); second is c+32

    const int g  = blockIdx.x >> 5;           // 32 blocks per graph
    const int cb = (blockIdx.x & 31) * CPB;   // center base (local)
    const int gb = g * NPG;

    if (tid < CPB) cnt[tid] = 0;

    // ---- load graph into smem: {x,y,z,|p|^2} (sq per reference rounding) ----
    for (int i = tid; i < NPG; i += THREADS) {
        const float* q = pos + 3ull * (unsigned long long)(gb + i);
        float x = q[0], y = q[1], z = q[2];
        float sq = __fadd_rn(__fadd_rn(__fmul_rn(x, x), __fmul_rn(y, y)),
                             __fmul_rn(z, z));
        sh[i] = make_float4(x, y, z, sq);
    }
    __syncthreads();

    const int lcA = cb + c;            // center A
    const int lcB = cb + c + 32;       // center B
    const float4 cA = sh[lcA];
    const float4 cB = sh[lcB];
    const float INF = __int_as_float(0x7f800000);

    // ---- pass 1: per part, 3 smallest for TWO centers off one load ----
    float a0 = INF, a1 = INF, a2 = INF;   // center A chain
    float b0 = INF, b1 = INF, b2 = INF;   // center B chain (independent -> ILP)
    const int jb = p * CANDS;
#pragma unroll 4
    for (int j = jb; j < jb + CANDS; ++j) {
        const float4 v = sh[j];                          // ONE load, two d2
        float dA = d2_ref(cA.x, cA.y, cA.z, cA.w, v);
        float dB = d2_ref(cB.x, cB.y, cB.z, cB.w, v);
        dA = (j == lcA) ? INF : dA;
        dB = (j == lcB) ? INF : dB;
        float t0 = fminf(a0, dA), x1 = fmaxf(a0, dA); a0 = t0;
        float t1 = fminf(a1, x1), x2 = fmaxf(a1, x1); a1 = t1;
        a2 = fminf(a2, x2);
        float s0 = fminf(b0, dB), y1 = fmaxf(b0, dB); b0 = s0;
        float s1 = fminf(b1, y1), y2 = fmaxf(b1, y1); b1 = s1;
        b2 = fminf(b2, y2);
    }
    {
        float* pvA = pvals + (c * PARTS + p) * 3;
        pvA[0] = a0; pvA[1] = a1; pvA[2] = a2;
        float* pvB = pvals + ((c + 32) * PARTS + p) * 3;
        pvB[0] = b0; pvB[1] = b1; pvB[2] = b2;
    }
    __syncthreads();

    // ---- bound per center: 16th smallest of its 24 part-values (9th largest) ----
    if (tid < CPB) {
        float g9[9];
#pragma unroll
        for (int t = 0; t < 9; ++t) g9[t] = -INF;
        const float* pv = pvals + tid * PARTS * 3;
        for (int e = 0; e < PARTS * 3; ++e) {
            float x = pv[e];
#pragma unroll
            for (int t = 0; t < 9; ++t) {
                float hi = fmaxf(g9[t], x);
                x = fminf(g9[t], x);
                g9[t] = hi;
            }
        }
        bnd[tid] = g9[8];   // >= true 16th smallest (16 distinct non-self
                            // elements of the union are <= it)
    }
    __syncthreads();

    // ---- pass 2: one load, two bound tests (self included, skipped later) ----
    const float BA = bnd[c];
    const float BB = bnd[c + 32];
#pragma unroll 4
    for (int j = jb; j < jb + CANDS; ++j) {
        const float4 v = sh[j];
        float dA = d2_ref(cA.x, cA.y, cA.z, cA.w, v);
        float dB = d2_ref(cB.x, cB.y, cB.z, cB.w, v);
        if (dA <= BA) {
            int s = atomicAdd(&cnt[c], 1);
            if (s < CAP) jbuf[c * CAP + s] = (unsigned short)j;
        }
        if (dB <= BB) {
            int s = atomicAdd(&cnt[c + 32], 1);
            if (s < CAP) jbuf[(c + 32) * CAP + s] = (unsigned short)j;
        }
    }
    __syncthreads();

    // ---- selection + filters + emit: one lane per center ----
    if (tid < CPB) {
        const int    lc2 = cb + tid;
        const float4 c0  = sh[lc2];
        const float  ax = c0.x, ay = c0.y, az = c0.z, asq = c0.w;

        unsigned long long hd[KNN];
#pragma unroll
        for (int t = 0; t < KNN; ++t) hd[t] = ~0ull;

        const int m = cnt[tid];
        if (m <= CAP) {
            for (int e = 0; e < m; ++e) {
                const int j = jbuf[tid * CAP + e];
                if (j == lc2) continue;          // skip self
                float d2 = d2_ref(ax, ay, az, asq, sh[j]);
                unsigned long long key =
                    ((unsigned long long)sortkey(d2) << 32) | (unsigned)j;
                if (key < hd[KNN - 1]) {
#pragma unroll
                    for (int t = 0; t < KNN; ++t) {
                        unsigned long long lo = key < hd[t] ? key : hd[t];
                        unsigned long long hi = key < hd[t] ? hd[t] : key;
                        hd[t] = lo; key = hi;
                    }
                }
            }
        } else {
            // overflow fallback: exact full scan (deterministic, ~never)
            for (int j = 0; j < NPG; ++j) {
                if (j == lc2) continue;
                float d2 = d2_ref(ax, ay, az, asq, sh[j]);
                unsigned long long key =
                    ((unsigned long long)sortkey(d2) << 32) | (unsigned)j;
                if (key < hd[KNN - 1]) {
#pragma unroll
                    for (int t = 0; t < KNN; ++t) {
                        unsigned long long lo = key < hd[t] ? key : hd[t];
                        unsigned long long hi = key < hd[t] ? hd[t] : key;
                        hd[t] = lo; key = hi;
                    }
                }
            }
        }

        const int ctr = gb + lc2;
#pragma unroll
        for (int k = 0; k < KNN; ++k) {
            float2 e = make_float2(-1.0f, -1.0f);
            if (hd[k] != ~0ull) {
                const int nl  = (int)(unsigned)(hd[k] & 0xFFFFFFFFull);
                const int nbr = gb + nl;
                const float4 v = sh[nl];
                // degenerate-edge filter, reference formula
                float dx = __fadd_rn(v.x, -ax);
                float dy = __fadd_rn(v.y, -ay);
                float dz = __fadd_rn(v.z, -az);
                float dn2 = __fadd_rn(__fadd_rn(__fmul_rn(dx, dx),
                                                __fmul_rn(dy, dy)),
                                      __fmul_rn(dz, dz));
                int  rd    = nbr > ctr ? (nbr - ctr) : (ctr - nbr);
                bool valid = (rd >= MIN_DISTR) && (sqrtf(dn2) >= 1e-10f);
                if (valid) e = make_float2((float)nbr, (float)ctr);
            }
            out[ctr * KNN + k] = e;
        }
    }
}

extern "C" void kernel_launch(void* const* d_in, const int* in_sizes, int n_in,
                              void* d_out, int out_size)
{
    const float* pos = (const float*)d_in[0];
    for (int i = 0; i < n_in; ++i)
        if (in_sizes[i] == BGRAPHS * NPG * 3) { pos = (const float*)d_in[i]; break; }
    float2* out = (float2*)d_out;

    dim3 grid(BGRAPHS * (NPG / CPB));   // 512 blocks: one wave at 4 blocks/SM
    dim3 block(THREADS);                // 256 threads
    knn_kernel<<<grid, block>>>(pos, out);
}